// round 13
// baseline (speedup 1.0000x reference)
#include <cuda_runtime.h>
#include <math.h>

// Problem constants (fixed by the reference: B=8192, V=8, J=32)
constexpr int BB = 8192;
constexpr int VV = 8;
constexpr int JJ = 32;
constexpr int PAIRS = BB * VV;                        // 65536 (b,v) problems
constexpr int WARPS_PER_BLOCK = 8;
constexpr int PAIRS_PER_WARP = 4;                     // 8-lane segments (best measured config)
constexpr int PAIRS_PER_BLOCK = WARPS_PER_BLOCK * PAIRS_PER_WARP;  // 32
constexpr int NBLOCKS = PAIRS / PAIRS_PER_BLOCK;      // 2048
constexpr float SCALE_KPS = 0.1f;
constexpr float ALPHA = 0.1f;
// log2(100^0.9) = 0.9 * log2(100)
constexpr float LOG2_TBETA = 5.979470570797252f;
constexpr double FIX = 262144.0;                      // 2^18 fixed-point scale

__device__ unsigned long long g_accum = 0ull;         // fixed-point grid sum
__device__ unsigned int g_ticket = 0u;                // completion counter

// single-MUFU approximate ops
__device__ __forceinline__ float frcp_fast(float x) {
    float r; asm("rcp.approx.f32 %0, %1;" : "=f"(r) : "f"(x)); return r;
}
__device__ __forceinline__ float fsqrt_fast(float x) {
    float r; asm("sqrt.approx.f32 %0, %1;" : "=f"(r) : "f"(x)); return r;
}
__device__ __forceinline__ float lg2_fast(float x) {
    float r; asm("lg2.approx.f32 %0, %1;" : "=f"(r) : "f"(x)); return r;
}
__device__ __forceinline__ float ex2_fast(float x) {
    float r; asm("ex2.approx.f32 %0, %1;" : "=f"(r) : "f"(x)); return r;
}

struct Acc { float pn2, in2, ls; };

__device__ __forceinline__ void do_joint(
    float X, float Y, float Z, float ix, float iy,
    const float4& c0, const float4& c1, const float4& c2,
    const float* __restrict__ kk, Acc& a)
{
    const float cx = c0.x * X + c0.y * Y + c0.z * Z + c0.w;
    const float cy = c1.x * X + c1.y * Y + c1.z * Z + c1.w;
    const float cz = c2.x * X + c2.y * Y + c2.z * Z + c2.w;
    const float px = kk[0] * cx + kk[1] * cy + kk[2] * cz;
    const float py = kk[3] * cx + kk[4] * cy + kk[5] * cz;
    const float pz = kk[6] * cx + kk[7] * cy + kk[8] * cz;
    const float iz = frcp_fast(pz);
    const float u = px * iz, w = py * iz;
    a.pn2 += u * u + w * w;
    a.in2 += ix * ix + iy * iy;
    float d0 = (u - ix) * SCALE_KPS; d0 = d0 * d0;
    float d1 = (w - iy) * SCALE_KPS; d1 = d1 * d1;
    // Smooth-MSE tail, EXACT via min-trick:
    //   T_BETA * d^0.1 crosses d precisely at d = THRESHOLD (=100), and lies
    //   above it for d < 100, below for d > 100. So
    //   where(d>100, T_BETA*d^0.1, d) == min(d, T_BETA*d^0.1).
    //   T_BETA is folded into the exponent: exp2(0.1*lg2(d) + log2(T_BETA)).
    // 1 FMNMX replaces FSETP+FSEL; 1 FMA absorbs the T_BETA multiply.
    const float e0 = ex2_fast(fmaf(lg2_fast(d0), ALPHA, LOG2_TBETA));
    const float e1 = ex2_fast(fmaf(lg2_fast(d1), ALPHA, LOG2_TBETA));
    a.ls += fminf(d0, e0) + fminf(d1, e1);
}

__global__ __launch_bounds__(WARPS_PER_BLOCK * 32, 6)   // best measured: regs=40, 48 warps/SM
void qpl_fused(const float* __restrict__ Kmat,
               const float* __restrict__ cam,
               const float* __restrict__ kps,
               const float* __restrict__ init,
               float* __restrict__ out) {
    const int t = threadIdx.x;
    const int warp = t >> 5;
    const int lane = t & 31;
    const int grp = lane >> 3;      // which of 4 pairs in this warp
    const int sub = lane & 7;       // lane in 8-lane group; handles joints 4*sub..4*sub+3
    const int pair = blockIdx.x * PAIRS_PER_BLOCK + warp * PAIRS_PER_WARP + grp;
    const int b = pair >> 3;        // 4 consecutive pairs share one batch

    // ---- loads: 16B-aligned vectors / group-uniform broadcast ----
    const float4* ikp = reinterpret_cast<const float4*>(init) + (size_t)pair * 16 + sub * 2;
    const float4 ia = ikp[0], ib = ikp[1];
    const float4* kp4 = reinterpret_cast<const float4*>(kps + (size_t)b * (JJ * 3) + sub * 12);
    const float4 q0 = kp4[0], q1 = kp4[1], q2 = kp4[2];
    const float4* C = reinterpret_cast<const float4*>(cam + (size_t)pair * 12);
    const float4 c0 = C[0], c1 = C[1], c2 = C[2];
    const float* Kp = Kmat + (size_t)pair * 9;
    float kk[9];
#pragma unroll
    for (int i = 0; i < 9; i++) kk[i] = Kp[i];

    Acc a = {0.0f, 0.0f, 0.0f};
    // 4 independent joint chains -> ILP hides MUFU/LDG latency
    do_joint(q0.x, q0.y, q0.z, ia.x, ia.y, c0, c1, c2, kk, a);
    do_joint(q0.w, q1.x, q1.y, ia.z, ia.w, c0, c1, c2, kk, a);
    do_joint(q1.z, q1.w, q2.x, ib.x, ib.y, c0, c1, c2, kk, a);
    do_joint(q2.y, q2.z, q2.w, ib.z, ib.w, c0, c1, c2, kk, a);

    // ---- segmented butterfly reduce within each 8-lane group ----
#pragma unroll
    for (int o = 4; o; o >>= 1) {
        a.pn2 += __shfl_xor_sync(0xFFFFFFFFu, a.pn2, o);
        a.in2 += __shfl_xor_sync(0xFFFFFFFFu, a.in2, o);
        a.ls  += __shfl_xor_sync(0xFFFFFFFFu, a.ls,  o);
    }

    __shared__ float sm[PAIRS_PER_BLOCK];
    if (sub == 0) {
        const float penal = fabsf(fsqrt_fast(a.pn2 * frcp_fast(a.in2)) - 1.0f);
        sm[warp * PAIRS_PER_WARP + grp] = penal * a.ls * 0.5f;
    }
    __syncthreads();

    // warp 0 reduces the 32 per-pair results
    if (warp == 0) {
        float s = sm[lane];
#pragma unroll
        for (int o = 16; o; o >>= 1) s += __shfl_xor_sync(0xFFFFFFFFu, s, o);
        if (lane == 0) {
            // order-invariant integer accumulation => deterministic grid sum
            const long long q = __double2ll_rn((double)s * FIX);
            atomicAdd(&g_accum, (unsigned long long)q);
            __threadfence();
            const unsigned int tk = atomicAdd(&g_ticket, 1u);
            if (tk == (unsigned int)(NBLOCKS - 1)) {
                const unsigned long long total = atomicAdd(&g_accum, 0ull);
                const double mean = ((double)(long long)total) / FIX / (double)PAIRS;
                out[0] = (float)mean;
                atomicExch(&g_accum, 0ull);
                __threadfence();
                atomicExch(&g_ticket, 0u);
            }
        }
    }
}

extern "C" void kernel_launch(void* const* d_in, const int* in_sizes, int n_in,
                              void* d_out, int out_size) {
    const float* Kmat = (const float*)d_in[0];  // [B,V,3,3]
    const float* cam  = (const float*)d_in[1];  // [B,V,3,4]
    const float* kps  = (const float*)d_in[2];  // [B,J,3]
    const float* init = (const float*)d_in[3];  // [B,V,J,2]
    float* out = (float*)d_out;

    qpl_fused<<<NBLOCKS, WARPS_PER_BLOCK * 32>>>(Kmat, cam, kps, init, out);
}

// round 14
// speedup vs baseline: 1.0022x; 1.0022x over previous
#include <cuda_runtime.h>
#include <math.h>

// Problem constants (fixed by the reference: B=8192, V=8, J=32)
constexpr int BB = 8192;
constexpr int VV = 8;
constexpr int JJ = 32;
constexpr int PAIRS = BB * VV;                        // 65536 (b,v) problems
constexpr int WARPS_PER_BLOCK = 8;
constexpr int PAIRS_PER_WARP = 4;                     // 8-lane segments
constexpr int PAIRS_PER_BLOCK = WARPS_PER_BLOCK * PAIRS_PER_WARP;  // 32
constexpr int NBLOCKS = PAIRS / PAIRS_PER_BLOCK;      // 2048
constexpr float SCALE_KPS = 0.1f;
constexpr float ALPHA = 0.1f;
constexpr float LOG2_TBETA = 5.979470570797252f;      // log2(100^0.9)
constexpr double FIX = 262144.0;                      // 2^18 fixed-point scale

__device__ unsigned long long g_accum = 0ull;
__device__ unsigned int g_ticket = 0u;

typedef unsigned long long ull;

// ---- scalar MUFU approx ----
__device__ __forceinline__ float frcp_fast(float x) {
    float r; asm("rcp.approx.f32 %0, %1;" : "=f"(r) : "f"(x)); return r;
}
__device__ __forceinline__ float fsqrt_fast(float x) {
    float r; asm("sqrt.approx.f32 %0, %1;" : "=f"(r) : "f"(x)); return r;
}
__device__ __forceinline__ float lg2_fast(float x) {
    float r; asm("lg2.approx.f32 %0, %1;" : "=f"(r) : "f"(x)); return r;
}
__device__ __forceinline__ float ex2_fast(float x) {
    float r; asm("ex2.approx.f32 %0, %1;" : "=f"(r) : "f"(x)); return r;
}

// ---- packed f32x2 ops (sm_103a; ptxas never emits FFMA2 from C++) ----
__device__ __forceinline__ ull pack2(float lo, float hi) {
    ull r; asm("mov.b64 %0, {%1, %2};" : "=l"(r) : "f"(lo), "f"(hi)); return r;
}
__device__ __forceinline__ void unpack2(ull v, float& lo, float& hi) {
    asm("mov.b64 {%0, %1}, %2;" : "=f"(lo), "=f"(hi) : "l"(v));
}
__device__ __forceinline__ ull fma2(ull a, ull b, ull c) {
    ull d; asm("fma.rn.f32x2 %0, %1, %2, %3;" : "=l"(d) : "l"(a), "l"(b), "l"(c)); return d;
}
__device__ __forceinline__ ull mul2(ull a, ull b) {
    ull d; asm("mul.rn.f32x2 %0, %1, %2;" : "=l"(d) : "l"(a), "l"(b)); return d;
}

// smooth-MSE tail (EXACT min-trick; T_BETA folded into exponent)
__device__ __forceinline__ float tail1(float d) {
    const float e = ex2_fast(fmaf(lg2_fast(d), ALPHA, LOG2_TBETA));
    return fminf(d, e);
}

// one packed stream: 2 joints. Mp[0..3]=row0 packed, Mp[4..7]=row1 packed,
// M[8..11]=row2 scalar (pz path feeds scalar rcp anyway).
__device__ __forceinline__ void joint_pair(
    float X0, float Y0, float Z0, float X1, float Y1, float Z1,
    float ix0, float iy0, float ix1, float iy1,
    const ull* __restrict__ Mp, const float* __restrict__ M,
    ull Sp, ull NSp, ull& pn2p, ull& in2p, float& ls)
{
    const ull Xp = pack2(X0, X1), Yp = pack2(Y0, Y1), Zp = pack2(Z0, Z1);
    const ull ixp = pack2(ix0, ix1), iyp = pack2(iy0, iy1);

    const ull pxp = fma2(Mp[0], Xp, fma2(Mp[1], Yp, fma2(Mp[2], Zp, Mp[3])));
    const ull pyp = fma2(Mp[4], Xp, fma2(Mp[5], Yp, fma2(Mp[6], Zp, Mp[7])));
    const float pz0 = fmaf(M[8], X0, fmaf(M[9], Y0, fmaf(M[10], Z0, M[11])));
    const float pz1 = fmaf(M[8], X1, fmaf(M[9], Y1, fmaf(M[10], Z1, M[11])));
    const ull izp = pack2(frcp_fast(pz0), frcp_fast(pz1));

    const ull up = mul2(pxp, izp);
    const ull wp = mul2(pyp, izp);
    pn2p = fma2(up, up, fma2(wp, wp, pn2p));
    in2p = fma2(ixp, ixp, fma2(iyp, iyp, in2p));

    // d = ((u - ix) * S)^2  ==  (u*S + ix*(-S))^2, packed
    const ull du = fma2(ixp, NSp, mul2(up, Sp));
    const ull dw = fma2(iyp, NSp, mul2(wp, Sp));
    const ull dusq = mul2(du, du);
    const ull dwsq = mul2(dw, dw);
    float a0, a1, b0, b1;
    unpack2(dusq, a0, a1);
    unpack2(dwsq, b0, b1);
    ls += tail1(a0) + tail1(b0) + tail1(a1) + tail1(b1);
}

__global__ __launch_bounds__(WARPS_PER_BLOCK * 32, 4)   // regs<=64: no cap-induced recompute
void qpl_fused(const float* __restrict__ Kmat,
               const float* __restrict__ cam,
               const float* __restrict__ kps,
               const float* __restrict__ init,
               float* __restrict__ out) {
    const int t = threadIdx.x;
    const int warp = t >> 5;
    const int lane = t & 31;
    const int grp = lane >> 3;      // which of 4 pairs in this warp
    const int sub = lane & 7;       // joints 4*sub..4*sub+3
    const int pair = blockIdx.x * PAIRS_PER_BLOCK + warp * PAIRS_PER_WARP + grp;
    const int b = pair >> 3;

    // ---- loads: 16B-aligned vectors / group-uniform broadcast ----
    const float4* ikp = reinterpret_cast<const float4*>(init) + (size_t)pair * 16 + sub * 2;
    const float4 ia = ikp[0], ib = ikp[1];
    const float4* kp4 = reinterpret_cast<const float4*>(kps + (size_t)b * (JJ * 3) + sub * 12);
    const float4 q0 = kp4[0], q1 = kp4[1], q2 = kp4[2];
    const float4* C = reinterpret_cast<const float4*>(cam + (size_t)pair * 12);
    const float4 c0 = C[0], c1 = C[1], c2 = C[2];
    const float* Kp = Kmat + (size_t)pair * 9;

    // ---- M = K @ cam (3x4): 36 scalar FMA, wide ILP; K+cam die here ----
    float M[12];
    {
        const float k0 = Kp[0], k1 = Kp[1], k2 = Kp[2];
        const float k3 = Kp[3], k4 = Kp[4], k5 = Kp[5];
        const float k6 = Kp[6], k7 = Kp[7], k8 = Kp[8];
        const float r0[4] = {c0.x, c0.y, c0.z, c0.w};
        const float r1[4] = {c1.x, c1.y, c1.z, c1.w};
        const float r2[4] = {c2.x, c2.y, c2.z, c2.w};
#pragma unroll
        for (int j = 0; j < 4; j++) {
            M[j]     = k0 * r0[j] + k1 * r1[j] + k2 * r2[j];
            M[4 + j] = k3 * r0[j] + k4 * r1[j] + k5 * r2[j];
            M[8 + j] = k6 * r0[j] + k7 * r1[j] + k8 * r2[j];
        }
    }
    // broadcast-pack rows 0,1 of M for the packed streams
    ull Mp[8];
#pragma unroll
    for (int j = 0; j < 8; j++) Mp[j] = pack2(M[j], M[j]);
    const ull Sp  = pack2(SCALE_KPS, SCALE_KPS);
    const ull NSp = pack2(-SCALE_KPS, -SCALE_KPS);

    ull pn2p = pack2(0.0f, 0.0f), in2p = pn2p;
    float ls = 0.0f;
    // two packed streams of 2 joints each
    joint_pair(q0.x, q0.y, q0.z, q0.w, q1.x, q1.y,
               ia.x, ia.y, ia.z, ia.w, Mp, M, Sp, NSp, pn2p, in2p, ls);
    joint_pair(q1.z, q1.w, q2.x, q2.y, q2.z, q2.w,
               ib.x, ib.y, ib.z, ib.w, Mp, M, Sp, NSp, pn2p, in2p, ls);

    float pn2, in2, h0, h1;
    unpack2(pn2p, h0, h1); pn2 = h0 + h1;
    unpack2(in2p, h0, h1); in2 = h0 + h1;

    // ---- segmented butterfly reduce within each 8-lane group ----
#pragma unroll
    for (int o = 4; o; o >>= 1) {
        pn2 += __shfl_xor_sync(0xFFFFFFFFu, pn2, o);
        in2 += __shfl_xor_sync(0xFFFFFFFFu, in2, o);
        ls  += __shfl_xor_sync(0xFFFFFFFFu, ls,  o);
    }

    __shared__ float sm[PAIRS_PER_BLOCK];
    if (sub == 0) {
        const float penal = fabsf(fsqrt_fast(pn2 * frcp_fast(in2)) - 1.0f);
        sm[warp * PAIRS_PER_WARP + grp] = penal * ls * 0.5f;
    }
    __syncthreads();

    // warp 0 reduces the 32 per-pair results
    if (warp == 0) {
        float s = sm[lane];
#pragma unroll
        for (int o = 16; o; o >>= 1) s += __shfl_xor_sync(0xFFFFFFFFu, s, o);
        if (lane == 0) {
            // order-invariant integer accumulation => deterministic grid sum
            const long long q = __double2ll_rn((double)s * FIX);
            atomicAdd(&g_accum, (unsigned long long)q);
            __threadfence();
            const unsigned int tk = atomicAdd(&g_ticket, 1u);
            if (tk == (unsigned int)(NBLOCKS - 1)) {
                const unsigned long long total = atomicAdd(&g_accum, 0ull);
                const double mean = ((double)(long long)total) / FIX / (double)PAIRS;
                out[0] = (float)mean;
                atomicExch(&g_accum, 0ull);
                __threadfence();
                atomicExch(&g_ticket, 0u);
            }
        }
    }
}

extern "C" void kernel_launch(void* const* d_in, const int* in_sizes, int n_in,
                              void* d_out, int out_size) {
    const float* Kmat = (const float*)d_in[0];  // [B,V,3,3]
    const float* cam  = (const float*)d_in[1];  // [B,V,3,4]
    const float* kps  = (const float*)d_in[2];  // [B,J,3]
    const float* init = (const float*)d_in[3];  // [B,V,J,2]
    float* out = (float*)d_out;

    qpl_fused<<<NBLOCKS, WARPS_PER_BLOCK * 32>>>(Kmat, cam, kps, init, out);
}